// round 6
// baseline (speedup 1.0000x reference)
#include <cuda_runtime.h>

typedef unsigned long long ull;

#define BATCH 1024
#define TLEN  200
#define DDIM  128
#define HDIM  128
#define NXC   384
#define MROWS (BATCH * TLEN)

__device__ float g_xproj[(size_t)MROWS * NXC];

// ---------- packed f32x2 helpers ----------
__device__ __forceinline__ ull dup2(float v) {
    ull r; asm("mov.b64 %0,{%1,%1};" : "=l"(r) : "f"(v)); return r;
}
__device__ __forceinline__ ull pack2(float x, float y) {
    ull r; asm("mov.b64 %0,{%1,%2};" : "=l"(r) : "f"(x), "f"(y)); return r;
}
__device__ __forceinline__ float2 unpack2(ull v) {
    float2 f; asm("mov.b64 {%0,%1},%2;" : "=f"(f.x), "=f"(f.y) : "l"(v)); return f;
}
__device__ __forceinline__ void ffma2(ull &d, ull a, ull b) {
    asm("fma.rn.f32x2 %0,%1,%2,%0;" : "+l"(d) : "l"(a), "l"(b));
}
__device__ __forceinline__ ull addf2(ull a, ull b) {
    ull r; asm("add.rn.f32x2 %0,%1,%2;" : "=l"(r) : "l"(a), "l"(b)); return r;
}
__device__ __forceinline__ float tanhap(float x) {
    float r; asm("tanh.approx.f32 %0,%1;" : "=f"(r) : "f"(x)); return r;
}
__device__ __forceinline__ float sigap(float x) {
    return fmaf(tanhap(0.5f * x), 0.5f, 0.5f);
}

// =====================================================================
// Phase 1 (unchanged R2 version): xproj = X @ Wx + bias.
// =====================================================================
__global__ void __launch_bounds__(256, 2) dien_xproj_kernel(
    const float* __restrict__ X, const int* __restrict__ seqlen,
    const float* __restrict__ Wg, const float* __restrict__ bg,
    const float* __restrict__ Wc, const float* __restrict__ bc)
{
    extern __shared__ float sm[];
    float* xsT = sm;
    float* ws  = sm + 64 * 132;

    const int tid = threadIdx.x;
    const int r0  = blockIdx.y * 128;
    const int ct  = blockIdx.x;

    __shared__ int anyv;
    if (tid == 0) anyv = 0;
    __syncthreads();
    if (tid < 128) {
        int r = r0 + tid;
        int b = r / TLEN, t = r - b * TLEN;
        if (t < seqlen[b]) anyv = 1;
    }
    __syncthreads();
    if (!anyv) return;

    const int tx = tid & 15;
    const int ty = tid >> 4;

    ull acc[8][4];
    {
        const float* bias = (ct < 2) ? (bg + ct * 128 + tx * 8) : (bc + tx * 8);
        #pragma unroll
        for (int p = 0; p < 4; p++) {
            ull bp = pack2(bias[2 * p], bias[2 * p + 1]);
            #pragma unroll
            for (int i = 0; i < 8; i++) acc[i][p] = bp;
        }
    }

    const float4* X4 = (const float4*)(X + (size_t)r0 * DDIM);

    for (int c = 0; c < 2; c++) {
        #pragma unroll
        for (int idx = tid; idx < 2048; idx += 256) {
            int k4 = idx >> 7;
            int r  = idx & 127;
            float4 v = X4[(size_t)r * 32 + c * 16 + k4];
            int kb = k4 * 4;
            xsT[(kb + 0) * 132 + r] = v.x;
            xsT[(kb + 1) * 132 + r] = v.y;
            xsT[(kb + 2) * 132 + r] = v.z;
            xsT[(kb + 3) * 132 + r] = v.w;
        }
        if (ct < 2) {
            const float4* W4 = (const float4*)Wg;
            #pragma unroll
            for (int idx = tid; idx < 2048; idx += 256) {
                int k = idx >> 5, c4 = idx & 31;
                *(float4*)&ws[k * 128 + c4 * 4] = W4[(c * 64 + k) * 64 + ct * 32 + c4];
            }
        } else {
            const float4* W4 = (const float4*)Wc;
            #pragma unroll
            for (int idx = tid; idx < 2048; idx += 256) {
                int k = idx >> 5, c4 = idx & 31;
                *(float4*)&ws[k * 128 + c4 * 4] = W4[(c * 64 + k) * 32 + c4];
            }
        }
        __syncthreads();

        const float4*     a4 = (const float4*)xsT;
        const ulonglong2* b2 = (const ulonglong2*)ws;

        #pragma unroll 4
        for (int k = 0; k < 64; k++) {
            float4 av0 = a4[k * 33 + ty * 2];
            float4 av1 = a4[k * 33 + ty * 2 + 1];
            ulonglong2 b01 = b2[k * 32 + tx * 2];
            ulonglong2 b23 = b2[k * 32 + tx * 2 + 1];
            ull A[8];
            A[0] = dup2(av0.x); A[1] = dup2(av0.y); A[2] = dup2(av0.z); A[3] = dup2(av0.w);
            A[4] = dup2(av1.x); A[5] = dup2(av1.y); A[6] = dup2(av1.z); A[7] = dup2(av1.w);
            #pragma unroll
            for (int i = 0; i < 8; i++) {
                ffma2(acc[i][0], A[i], b01.x);
                ffma2(acc[i][1], A[i], b01.y);
                ffma2(acc[i][2], A[i], b23.x);
                ffma2(acc[i][3], A[i], b23.y);
            }
        }
        __syncthreads();
    }

    #pragma unroll
    for (int i = 0; i < 8; i++) {
        size_t r = (size_t)(r0 + ty * 8 + i);
        float2 p0 = unpack2(acc[i][0]);
        float2 p1 = unpack2(acc[i][1]);
        float2 p2 = unpack2(acc[i][2]);
        float2 p3 = unpack2(acc[i][3]);
        float* dst = &g_xproj[r * NXC + ct * 128 + tx * 8];
        ((float4*)dst)[0] = make_float4(p0.x, p0.y, p1.x, p1.y);
        ((float4*)dst)[1] = make_float4(p2.x, p2.y, p3.x, p3.y);
    }
}

// =====================================================================
// Phase 2: fully thread-local GRU. 128 CTAs x 512 thr, 8 rows each.
// Thread (jc, P): gate lanes=(r,u) with packed (wr,wu) smem weights;
// cand lanes=(k-even,k-odd) partial sums, folded locally.
// No reductions, no staging, 2 barriers/step.
// =====================================================================
#define WGP_ROW 130     // ull per jc row (128 + 2 pad)
#define WCT_ROW 132     // floats per jc row
#define H_ROW   132     // floats per batch-row

__global__ void __launch_bounds__(512, 1) dien_gru_kernel(
    const float* __restrict__ Wg, const float* __restrict__ Wc,
    const int* __restrict__ seqlen, float* __restrict__ out)
{
    extern __shared__ char smraw[];
    ull*   wgP  = (ull*)smraw;                        // [128 jc][130] (wr,wu) pairs  133120 B
    float* wcT  = (float*)(smraw + 133120);           // [128 jc][132]                 67584 B
    float* hsm  = (float*)(smraw + 133120 + 67584);   // [8 row][132]                   4224 B
    float* rhsm = hsm + 8 * H_ROW;                    // [8 row][132]                   4224 B

    const int tid   = threadIdx.x;
    const int rows0 = blockIdx.x * 8;
    const int lane  = tid & 31;
    const int w     = tid >> 5;
    const int jl    = lane & 7;
    const int P     = lane >> 3;          // row pair 0..3
    const int jc    = w * 8 + jl;         // column 0..127
    const int rowa  = 2 * P, rowb = 2 * P + 1;

    // ---- preamble: pack gate weights (wr,wu), transpose cand weights ----
    for (int i = tid; i < 128 * 128; i += 512) {
        int k = i >> 7, j = i & 127;
        float wr = Wg[(size_t)(128 + k) * 256 + j];
        float wu = Wg[(size_t)(128 + k) * 256 + j + 128];
        wgP[j * WGP_ROW + k] = pack2(wr, wu);
        wcT[j * WCT_ROW + k] = Wc[(size_t)(128 + k) * 128 + j];
    }
    for (int i = tid; i < 8 * H_ROW; i += 512) hsm[i] = 0.0f;

    const int sqa = seqlen[rows0 + rowa];
    const int sqb = seqlen[rows0 + rowb];
    int maxseq = 0;
    #pragma unroll
    for (int i = 0; i < 8; i++) maxseq = max(maxseq, seqlen[rows0 + i]);
    __syncthreads();

    const ulonglong2* wg2 = (const ulonglong2*)(wgP + jc * WGP_ROW);
    const ulonglong2* wc2 = (const ulonglong2*)(wcT + jc * WCT_ROW);
    const float4*     ha4 = (const float4*)(hsm  + rowa * H_ROW);
    const float4*     hb4 = (const float4*)(hsm  + rowb * H_ROW);
    const ulonglong2* ra2 = (const ulonglong2*)(rhsm + rowa * H_ROW);
    const ulonglong2* rb2 = (const ulonglong2*)(rhsm + rowb * H_ROW);

    const float* xa = g_xproj + (size_t)(rows0 + rowa) * TLEN * NXC + jc;
    const float* xb = g_xproj + (size_t)(rows0 + rowb) * TLEN * NXC + jc;
    float* outa = out + (size_t)(rows0 + rowa) * TLEN * HDIM + jc;
    float* outb = out + (size_t)(rows0 + rowb) * TLEN * HDIM + jc;

    for (int t = 0; t < maxseq; t++) {
        // prefetch x-projections (consumed after the GEMV loops)
        const float* x0 = xa + (size_t)t * NXC;
        const float* x1 = xb + (size_t)t * NXC;
        float xra = x0[0], xua = x0[128], xca = x0[256];
        float xrb = x1[0], xub = x1[128], xcb = x1[256];

        // ---- gate GEMV: lanes = (r,u); rows a,b; 128 k ----
        ull aa0 = 0, aa1 = 0, ab0 = 0, ab1 = 0;
        #pragma unroll
        for (int i = 0; i < 32; i++) {
            ulonglong2 wa = wg2[2 * i];
            ulonglong2 wb = wg2[2 * i + 1];
            float4 hA = ha4[i];
            float4 hB = hb4[i];
            ffma2(aa0, dup2(hA.x), wa.x); ffma2(aa1, dup2(hA.y), wa.y);
            ffma2(ab0, dup2(hB.x), wa.x); ffma2(ab1, dup2(hB.y), wa.y);
            ffma2(aa0, dup2(hA.z), wb.x); ffma2(aa1, dup2(hA.w), wb.y);
            ffma2(ab0, dup2(hB.z), wb.x); ffma2(ab1, dup2(hB.w), wb.y);
        }
        float2 Za = unpack2(addf2(aa0, aa1));   // (zr, zu) row a
        float2 Zb = unpack2(addf2(ab0, ab1));
        float r_a = sigap(Za.x + xra), u_a = sigap(Za.y + xua);
        float r_b = sigap(Zb.x + xrb), u_b = sigap(Zb.y + xub);
        float Hoa = hsm[rowa * H_ROW + jc];
        float Hob = hsm[rowb * H_ROW + jc];
        rhsm[rowa * H_ROW + jc] = r_a * Hoa;
        rhsm[rowb * H_ROW + jc] = r_b * Hob;
        __syncthreads();

        // ---- cand GEMV: lanes = k-parity partials; rows a,b ----
        ull ca0 = 0, ca1 = 0, cb0 = 0, cb1 = 0;
        #pragma unroll
        for (int i = 0; i < 32; i++) {
            ulonglong2 wc = wc2[i];     // (k4i,k4i+1),(k4i+2,k4i+3)
            ulonglong2 ra = ra2[i];
            ulonglong2 rb = rb2[i];
            ffma2(ca0, ra.x, wc.x); ffma2(ca1, ra.y, wc.y);
            ffma2(cb0, rb.x, wc.x); ffma2(cb1, rb.y, wc.y);
        }
        float2 Fa = unpack2(addf2(ca0, ca1));
        float2 Fb = unpack2(addf2(cb0, cb1));
        float c_a = tanhap(Fa.x + Fa.y + xca);
        float c_b = tanhap(Fb.x + Fb.y + xcb);
        float hna = fmaf(u_a, Hoa - c_a, c_a);   // u*h + (1-u)*c
        float hnb = fmaf(u_b, Hob - c_b, c_b);
        bool va = t < sqa, vb = t < sqb;
        hsm[rowa * H_ROW + jc] = va ? hna : Hoa;
        hsm[rowb * H_ROW + jc] = vb ? hnb : Hob;
        if (va) outa[(size_t)t * HDIM] = hna;
        if (vb) outb[(size_t)t * HDIM] = hnb;
        __syncthreads();
    }
}

// =====================================================================
extern "C" void kernel_launch(void* const* d_in, const int* in_sizes, int n_in,
                              void* d_out, int out_size)
{
    const float* X   = (const float*)d_in[0];
    const int*   seq = (const int*)  d_in[1];
    const float* Wg  = (const float*)d_in[2];
    const float* bg  = (const float*)d_in[3];
    const float* Wc  = (const float*)d_in[4];
    const float* bc  = (const float*)d_in[5];
    float* out = (float*)d_out;
    (void)in_sizes; (void)n_in;

    const int SMEM1 = (64 * 132 + 64 * 128) * 4;              // 66560 B
    const int SMEM2 = 133120 + 67584 + 2 * 8 * H_ROW * 4;     // 209152 B
    cudaFuncSetAttribute(dien_xproj_kernel, cudaFuncAttributeMaxDynamicSharedMemorySize, SMEM1);
    cudaFuncSetAttribute(dien_gru_kernel,   cudaFuncAttributeMaxDynamicSharedMemorySize, SMEM2);

    cudaMemsetAsync(d_out, 0, (size_t)out_size * sizeof(float));

    dim3 g1(3, MROWS / 128);
    dien_xproj_kernel<<<g1, 256, SMEM1>>>(X, seq, Wg, bg, Wc, bc);
    dien_gru_kernel<<<BATCH / 8, 512, SMEM2>>>(Wg, Wc, seq, out);
}

// round 7
// speedup vs baseline: 1.8738x; 1.8738x over previous
#include <cuda_runtime.h>

typedef unsigned long long ull;

#define BATCH 1024
#define TLEN  200
#define DDIM  128
#define HDIM  128
#define NXC   384
#define MROWS (BATCH * TLEN)
#define GROUPS 256

__device__ float g_xproj[(size_t)MROWS * NXC];
__device__ int   g_perm[BATCH];

// ---------- packed f32x2 helpers ----------
__device__ __forceinline__ ull dup2(float v) {
    ull r; asm("mov.b64 %0,{%1,%1};" : "=l"(r) : "f"(v)); return r;
}
__device__ __forceinline__ ull pack2(float x, float y) {
    ull r; asm("mov.b64 %0,{%1,%2};" : "=l"(r) : "f"(x), "f"(y)); return r;
}
__device__ __forceinline__ float2 unpack2(ull v) {
    float2 f; asm("mov.b64 {%0,%1},%2;" : "=f"(f.x), "=f"(f.y) : "l"(v)); return f;
}
__device__ __forceinline__ void ffma2(ull &d, ull a, ull b) {
    asm("fma.rn.f32x2 %0,%1,%2,%0;" : "+l"(d) : "l"(a), "l"(b));
}
__device__ __forceinline__ ull addf2(ull a, ull b) {
    ull r; asm("add.rn.f32x2 %0,%1,%2;" : "=l"(r) : "l"(a), "l"(b)); return r;
}
__device__ __forceinline__ float tanhap(float x) {
    float r; asm("tanh.approx.f32 %0,%1;" : "=f"(r) : "f"(x)); return r;
}
__device__ __forceinline__ float sigap(float x) {
    return fmaf(tanhap(0.5f * x), 0.5f, 0.5f);
}

// =====================================================================
// Kernel 0: counting sort of batch rows by seq_len, DESCENDING -> g_perm
// =====================================================================
__global__ void __launch_bounds__(1024) dien_sort_kernel(const int* __restrict__ seq)
{
    __shared__ int s[1024];
    __shared__ int cnt[256];
    __shared__ int cur[256];
    __shared__ int buf[256];
    const int tid = threadIdx.x;

    s[tid] = seq[tid];
    if (tid < 256) { cnt[tid] = 0; cur[tid] = 0; }
    __syncthreads();
    atomicAdd(&cnt[s[tid] & 255], 1);
    __syncthreads();
    if (tid < 256) buf[tid] = cnt[tid];
    __syncthreads();
    // suffix sum: buf[v] = # rows with len >= v
    for (int off = 1; off < 256; off <<= 1) {
        int v = 0;
        if (tid < 256) { v = buf[tid]; if (tid + off < 256) v += buf[tid + off]; }
        __syncthreads();
        if (tid < 256) buf[tid] = v;
        __syncthreads();
    }
    {
        int v = s[tid] & 255;
        int start = buf[v] - cnt[v];          // # rows with len > v
        int rank = atomicAdd(&cur[v], 1);
        g_perm[start + rank] = tid;
    }
}

// =====================================================================
// Phase 1 (R2 version): xproj = X @ Wx + bias. BM128 x BN128, K 2x64,
// 256 thr, 2 CTAs/SM. Dead tiles skipped via seq_len.
// =====================================================================
__global__ void __launch_bounds__(256, 2) dien_xproj_kernel(
    const float* __restrict__ X, const int* __restrict__ seqlen,
    const float* __restrict__ Wg, const float* __restrict__ bg,
    const float* __restrict__ Wc, const float* __restrict__ bc)
{
    extern __shared__ float sm[];
    float* xsT = sm;
    float* ws  = sm + 64 * 132;

    const int tid = threadIdx.x;
    const int r0  = blockIdx.y * 128;
    const int ct  = blockIdx.x;

    __shared__ int anyv;
    if (tid == 0) anyv = 0;
    __syncthreads();
    if (tid < 128) {
        int r = r0 + tid;
        int b = r / TLEN, t = r - b * TLEN;
        if (t < seqlen[b]) anyv = 1;
    }
    __syncthreads();
    if (!anyv) return;

    const int tx = tid & 15;
    const int ty = tid >> 4;

    ull acc[8][4];
    {
        const float* bias = (ct < 2) ? (bg + ct * 128 + tx * 8) : (bc + tx * 8);
        #pragma unroll
        for (int p = 0; p < 4; p++) {
            ull bp = pack2(bias[2 * p], bias[2 * p + 1]);
            #pragma unroll
            for (int i = 0; i < 8; i++) acc[i][p] = bp;
        }
    }

    const float4* X4 = (const float4*)(X + (size_t)r0 * DDIM);

    for (int c = 0; c < 2; c++) {
        #pragma unroll
        for (int idx = tid; idx < 2048; idx += 256) {
            int k4 = idx >> 7;
            int r  = idx & 127;
            float4 v = X4[(size_t)r * 32 + c * 16 + k4];
            int kb = k4 * 4;
            xsT[(kb + 0) * 132 + r] = v.x;
            xsT[(kb + 1) * 132 + r] = v.y;
            xsT[(kb + 2) * 132 + r] = v.z;
            xsT[(kb + 3) * 132 + r] = v.w;
        }
        if (ct < 2) {
            const float4* W4 = (const float4*)Wg;
            #pragma unroll
            for (int idx = tid; idx < 2048; idx += 256) {
                int k = idx >> 5, c4 = idx & 31;
                *(float4*)&ws[k * 128 + c4 * 4] = W4[(c * 64 + k) * 64 + ct * 32 + c4];
            }
        } else {
            const float4* W4 = (const float4*)Wc;
            #pragma unroll
            for (int idx = tid; idx < 2048; idx += 256) {
                int k = idx >> 5, c4 = idx & 31;
                *(float4*)&ws[k * 128 + c4 * 4] = W4[(c * 64 + k) * 32 + c4];
            }
        }
        __syncthreads();

        const float4*     a4 = (const float4*)xsT;
        const ulonglong2* b2 = (const ulonglong2*)ws;

        #pragma unroll 4
        for (int k = 0; k < 64; k++) {
            float4 av0 = a4[k * 33 + ty * 2];
            float4 av1 = a4[k * 33 + ty * 2 + 1];
            ulonglong2 b01 = b2[k * 32 + tx * 2];
            ulonglong2 b23 = b2[k * 32 + tx * 2 + 1];
            ull A[8];
            A[0] = dup2(av0.x); A[1] = dup2(av0.y); A[2] = dup2(av0.z); A[3] = dup2(av0.w);
            A[4] = dup2(av1.x); A[5] = dup2(av1.y); A[6] = dup2(av1.z); A[7] = dup2(av1.w);
            #pragma unroll
            for (int i = 0; i < 8; i++) {
                ffma2(acc[i][0], A[i], b01.x);
                ffma2(acc[i][1], A[i], b01.y);
                ffma2(acc[i][2], A[i], b23.x);
                ffma2(acc[i][3], A[i], b23.y);
            }
        }
        __syncthreads();
    }

    #pragma unroll
    for (int i = 0; i < 8; i++) {
        size_t r = (size_t)(r0 + ty * 8 + i);
        float2 p0 = unpack2(acc[i][0]);
        float2 p1 = unpack2(acc[i][1]);
        float2 p2 = unpack2(acc[i][2]);
        float2 p3 = unpack2(acc[i][3]);
        float* dst = &g_xproj[r * NXC + ct * 128 + tx * 8];
        ((float4*)dst)[0] = make_float4(p0.x, p0.y, p1.x, p1.y);
        ((float4*)dst)[1] = make_float4(p2.x, p2.y, p3.x, p3.y);
    }
}

// =====================================================================
// Phase 2: R2-structure GRU on sorted 4-row groups. 256 CTAs x 512 thr.
// CTA g: rows g_perm[4g..4g+4). thread (jc, q): col jc, k-split 16 k.
// Gate weights register-resident (pre-duplicated). Warp-uniform q ->
// all h/rh loads are broadcasts. Staging 6 ull/thread, 4 barriers/step.
// =====================================================================
__global__ void __launch_bounds__(512, 1) dien_gru_kernel(
    const float* __restrict__ Wg, const float* __restrict__ Wc,
    const int* __restrict__ seqlen, float* __restrict__ out)
{
    extern __shared__ char smraw[];
    float* whc = (float*)smraw;                 // [128 k][128 col]   65536 B
    ull*   hp  = (ull*)(smraw + 65536);         // [2 pair][128 k]     2048 B
    ull*   rhp = hp + 256;                      // [2 pair][128 k]     2048 B
    ull*   red = rhp + 256;                     // 4096 ull           32768 B

    const int tid = threadIdx.x;
    const int jc  = tid & 127;
    const int q   = tid >> 7;            // 0..3? no: 512/128 = 4 -> q 0..3
    // NOTE: with 512 threads and 128 cols we have q in 0..3, k-split 32.
    const int k0  = q * 32;

    // ---- cand h-weights into smem ([k][col], direct copy of lower half) ----
    for (int i = tid; i < 128 * 128; i += 512) whc[i] = Wc[128 * 128 + i];

    // ---- gate weights: 32 k's x 2 gates, pre-duplicated (128 regs would be
    // too many; keep as floats, dup at use) ----
    float wgr[32], wgu[32];
    #pragma unroll
    for (int i = 0; i < 32; i++) {
        wgr[i] = Wg[(size_t)(128 + k0 + i) * 256 + jc];
        wgu[i] = Wg[(size_t)(128 + k0 + i) * 256 + jc + 128];
    }

    const int g  = blockIdx.x;
    int rA0 = g_perm[4 * g],     rB0 = g_perm[4 * g + 1];
    int rA1 = g_perm[4 * g + 2], rB1 = g_perm[4 * g + 3];
    const int maxseq = seqlen[rA0];      // sorted desc -> first is max

    // epilogue threads: q<2 own pair P=q (rows (rA,rB))
    const int rowA = (q == 0) ? rA0 : rA1;
    const int rowB = (q == 0) ? rB0 : rB1;
    const int sqa = seqlen[rowA];
    const int sqb = seqlen[rowB];

    if (tid < 256) hp[tid] = 0ull;
    __syncthreads();

    const float* xa = g_xproj + (size_t)rowA * TLEN * NXC + jc;
    const float* xb = g_xproj + (size_t)rowB * TLEN * NXC + jc;
    float* oa = out + (size_t)rowA * TLEN * HDIM + jc;
    float* ob = out + (size_t)rowB * TLEN * HDIM + jc;

    const ulonglong2* h2 = (const ulonglong2*)hp  + (k0 >> 1);
    const ulonglong2* r2 = (const ulonglong2*)rhp + (k0 >> 1);
    const float* wcp = whc + k0 * 128 + jc;

    for (int t = 0; t < maxseq; t++) {
        // prefetch x-projections (epilogue threads, consumed after GEMVs)
        float xra = 0.f, xrb = 0.f, xua = 0.f, xub = 0.f, xca = 0.f, xcb = 0.f;
        if (q < 2) {
            const float* p0 = xa + (size_t)t * NXC;
            const float* p1 = xb + (size_t)t * NXC;
            if (t < sqa) { xra = p0[0]; xua = p0[128]; xca = p0[256]; }
            if (t < sqb) { xrb = p1[0]; xub = p1[128]; xcb = p1[256]; }
        }

        // ---- gate GEMV: 2 gates x 2 pairs, 32 k from regs ----
        ull ar0 = 0, ar1 = 0, au0 = 0, au1 = 0;
        #pragma unroll
        for (int i = 0; i < 16; i++) {
            ulonglong2 a0 = h2[i];          // pair 0, k = k0+2i (broadcast)
            ulonglong2 a1 = h2[64 + i];     // pair 1
            ull w0 = dup2(wgr[2 * i]), w1 = dup2(wgr[2 * i + 1]);
            ull v0 = dup2(wgu[2 * i]), v1 = dup2(wgu[2 * i + 1]);
            ffma2(ar0, a0.x, w0); ffma2(ar0, a0.y, w1);
            ffma2(ar1, a1.x, w0); ffma2(ar1, a1.y, w1);
            ffma2(au0, a0.x, v0); ffma2(au0, a0.y, v1);
            ffma2(au1, a1.x, v0); ffma2(au1, a1.y, v1);
        }
        // stage: red[q*1024 + {r:0,u:512} + P*128 + jc]
        {
            ull* st = red + q * 1024 + jc;
            st[0]   = ar0; st[128] = ar1;
            st[512] = au0; st[640] = au1;
        }
        __syncthreads();

        // ---- gate epilogue (q<2): pair P=q, col jc ----
        float r_a, r_b, u_a, u_b; float2 Ho;
        if (q < 2) {
            const ull* rd = red + q * 128 + jc;
            ull zr = rd[0], zu = rd[512];
            #pragma unroll
            for (int qq = 1; qq < 4; qq++) {
                zr = addf2(zr, rd[qq * 1024]);
                zu = addf2(zu, rd[qq * 1024 + 512]);
            }
            float2 Zr = unpack2(zr), Zu = unpack2(zu);
            r_a = sigap(Zr.x + xra); r_b = sigap(Zr.y + xrb);
            u_a = sigap(Zu.x + xua); u_b = sigap(Zu.y + xub);
            Ho = unpack2(hp[q * 128 + jc]);
            rhp[q * 128 + jc] = pack2(r_a * Ho.x, r_b * Ho.y);
        }
        __syncthreads();

        // ---- cand GEMV: 2 pairs, 32 k, weights from smem ----
        ull c0 = 0, c1 = 0;
        #pragma unroll
        for (int i = 0; i < 16; i++) {
            ulonglong2 a0 = r2[i];
            ulonglong2 a1 = r2[64 + i];
            ull w0 = dup2(wcp[(2 * i) * 128]);
            ull w1 = dup2(wcp[(2 * i + 1) * 128]);
            ffma2(c0, a0.x, w0); ffma2(c0, a0.y, w1);
            ffma2(c1, a1.x, w0); ffma2(c1, a1.y, w1);
        }
        {
            ull* st = red + q * 256 + jc;
            st[0] = c0; st[128] = c1;
        }
        __syncthreads();

        // ---- cand epilogue + state update (q<2) ----
        if (q < 2) {
            const ull* rd = red + q * 128 + jc;
            ull zc = rd[0];
            #pragma unroll
            for (int qq = 1; qq < 4; qq++) zc = addf2(zc, rd[qq * 256]);
            float2 Zc = unpack2(zc);
            float c_a = tanhap(Zc.x + xca);
            float c_b = tanhap(Zc.y + xcb);
            float hna = fmaf(u_a, Ho.x - c_a, c_a);
            float hnb = fmaf(u_b, Ho.y - c_b, c_b);
            bool va = t < sqa, vb = t < sqb;
            hp[q * 128 + jc] = pack2(va ? hna : Ho.x, vb ? hnb : Ho.y);
            if (va) oa[(size_t)t * HDIM] = hna;
            if (vb) ob[(size_t)t * HDIM] = hnb;
        }
        __syncthreads();
    }
}

// =====================================================================
extern "C" void kernel_launch(void* const* d_in, const int* in_sizes, int n_in,
                              void* d_out, int out_size)
{
    const float* X   = (const float*)d_in[0];
    const int*   seq = (const int*)  d_in[1];
    const float* Wg  = (const float*)d_in[2];
    const float* bg  = (const float*)d_in[3];
    const float* Wc  = (const float*)d_in[4];
    const float* bc  = (const float*)d_in[5];
    float* out = (float*)d_out;
    (void)in_sizes; (void)n_in;

    const int SMEM1 = (64 * 132 + 64 * 128) * 4;          // 66560 B
    const int SMEM2 = 65536 + 2048 + 2048 + 32768;        // 102400 B
    cudaFuncSetAttribute(dien_xproj_kernel, cudaFuncAttributeMaxDynamicSharedMemorySize, SMEM1);
    cudaFuncSetAttribute(dien_gru_kernel,   cudaFuncAttributeMaxDynamicSharedMemorySize, SMEM2);

    cudaMemsetAsync(d_out, 0, (size_t)out_size * sizeof(float));

    dien_sort_kernel<<<1, 1024>>>(seq);
    dim3 g1(3, MROWS / 128);
    dien_xproj_kernel<<<g1, 256, SMEM1>>>(X, seq, Wg, bg, Wc, bc);
    dien_gru_kernel<<<GROUPS, 512, SMEM2>>>(Wg, Wc, seq, out);
}

// round 8
// speedup vs baseline: 2.4122x; 1.2873x over previous
#include <cuda_runtime.h>

typedef unsigned long long ull;

#define BATCH 1024
#define TLEN  200
#define DDIM  128
#define HDIM  128
#define NXC   384
#define MROWS (BATCH * TLEN)
#define GROUPS 256

// compact x-projection (sorted-row-major) + perm/offsets
__device__ float g_xproj[(size_t)MROWS * NXC];
__device__ int   g_perm[BATCH];
__device__ int   g_coff[BATCH + 1];

// ---------- packed f32x2 helpers ----------
__device__ __forceinline__ ull dup2(float v) {
    ull r; asm("mov.b64 %0,{%1,%1};" : "=l"(r) : "f"(v)); return r;
}
__device__ __forceinline__ ull pack2(float x, float y) {
    ull r; asm("mov.b64 %0,{%1,%2};" : "=l"(r) : "f"(x), "f"(y)); return r;
}
__device__ __forceinline__ float2 unpack2(ull v) {
    float2 f; asm("mov.b64 {%0,%1},%2;" : "=f"(f.x), "=f"(f.y) : "l"(v)); return f;
}
__device__ __forceinline__ void ffma2(ull &d, ull a, ull b) {
    asm("fma.rn.f32x2 %0,%1,%2,%0;" : "+l"(d) : "l"(a), "l"(b));
}
__device__ __forceinline__ ull addf2(ull a, ull b) {
    ull r; asm("add.rn.f32x2 %0,%1,%2;" : "=l"(r) : "l"(a), "l"(b)); return r;
}
__device__ __forceinline__ float tanhap(float x) {
    float r; asm("tanh.approx.f32 %0,%1;" : "=f"(r) : "f"(x)); return r;
}
__device__ __forceinline__ float sigap(float x) {
    return fmaf(tanhap(0.5f * x), 0.5f, 0.5f);
}

// =====================================================================
// Kernel 0: counting sort rows by seq_len DESC -> g_perm; exclusive
// prefix sum of sorted lengths -> g_coff[0..1024].
// =====================================================================
__global__ void __launch_bounds__(1024) dien_sort_kernel(const int* __restrict__ seq)
{
    __shared__ int s[1024];
    __shared__ int sperm[1024];
    __shared__ int cnt[256];
    __shared__ int cur[256];
    __shared__ int buf[1024];
    const int tid = threadIdx.x;

    s[tid] = seq[tid];
    if (tid < 256) { cnt[tid] = 0; cur[tid] = 0; }
    __syncthreads();
    atomicAdd(&cnt[s[tid] & 255], 1);
    __syncthreads();
    if (tid < 256) buf[tid] = cnt[tid];
    __syncthreads();
    // suffix sum over buckets: buf[v] = # rows with len >= v
    for (int off = 1; off < 256; off <<= 1) {
        int v = 0;
        if (tid < 256) { v = buf[tid]; if (tid + off < 256) v += buf[tid + off]; }
        __syncthreads();
        if (tid < 256) buf[tid] = v;
        __syncthreads();
    }
    {
        int v = s[tid] & 255;
        int start = buf[v] - cnt[v];          // # rows with len > v
        int rank = atomicAdd(&cur[v], 1);
        sperm[start + rank] = tid;
    }
    __syncthreads();
    g_perm[tid] = sperm[tid];
    // inclusive prefix of sorted lengths
    int sl = s[sperm[tid]];
    buf[tid] = sl;
    __syncthreads();
    for (int off = 1; off < 1024; off <<= 1) {
        int v = buf[tid] + ((tid >= off) ? buf[tid - off] : 0);
        __syncthreads();
        buf[tid] = v;
        __syncthreads();
    }
    g_coff[tid] = buf[tid] - sl;              // exclusive
    if (tid == 1023) g_coff[1024] = buf[1023];
}

// =====================================================================
// Phase 1: COMPACT xproj. Virtual row vr in sorted-compact space maps
// to (batch, t) via binary search in coff. Only valid rows computed.
// BM128 x BN128, K 2x64, 256 thr, 2 CTAs/SM.
// =====================================================================
__global__ void __launch_bounds__(256, 2) dien_xproj_kernel(
    const float* __restrict__ X,
    const float* __restrict__ Wg, const float* __restrict__ bg,
    const float* __restrict__ Wc, const float* __restrict__ bc)
{
    extern __shared__ float sm[];
    float* xsT = sm;                    // [64 k][132 rows]
    float* ws  = sm + 64 * 132;         // [64 k][128 cols]
    __shared__ int scoff[1025];
    __shared__ int srcrow[128];

    const int tid = threadIdx.x;
    const int r0  = blockIdx.y * 128;
    const int ct  = blockIdx.x;

    const int total = g_coff[1024];
    if (r0 >= total) return;

    for (int i = tid; i < 1025; i += 256) scoff[i] = g_coff[i];
    __syncthreads();
    if (tid < 128) {
        int vr = r0 + tid;
        int sr = -1;
        if (vr < total) {
            int lo = 0, hi = 1024;          // invariant: scoff[lo] <= vr < scoff[hi]
            while (hi - lo > 1) {
                int mid = (lo + hi) >> 1;
                if (scoff[mid] <= vr) lo = mid; else hi = mid;
            }
            sr = g_perm[lo] * TLEN + (vr - scoff[lo]);
        }
        srcrow[tid] = sr;
    }
    __syncthreads();

    const int tx = tid & 15;
    const int ty = tid >> 4;

    ull acc[8][4];
    {
        const float* bias = (ct < 2) ? (bg + ct * 128 + tx * 8) : (bc + tx * 8);
        #pragma unroll
        for (int p = 0; p < 4; p++) {
            ull bp = pack2(bias[2 * p], bias[2 * p + 1]);
            #pragma unroll
            for (int i = 0; i < 8; i++) acc[i][p] = bp;
        }
    }

    const float4* X4 = (const float4*)X;

    for (int c = 0; c < 2; c++) {
        #pragma unroll
        for (int idx = tid; idx < 2048; idx += 256) {
            int k4 = idx >> 7;
            int r  = idx & 127;
            int sr = srcrow[r];
            float4 v = make_float4(0.f, 0.f, 0.f, 0.f);
            if (sr >= 0) v = X4[(size_t)sr * 32 + c * 16 + k4];
            int kb = k4 * 4;
            xsT[(kb + 0) * 132 + r] = v.x;
            xsT[(kb + 1) * 132 + r] = v.y;
            xsT[(kb + 2) * 132 + r] = v.z;
            xsT[(kb + 3) * 132 + r] = v.w;
        }
        if (ct < 2) {
            const float4* W4 = (const float4*)Wg;
            #pragma unroll
            for (int idx = tid; idx < 2048; idx += 256) {
                int k = idx >> 5, c4 = idx & 31;
                *(float4*)&ws[k * 128 + c4 * 4] = W4[(c * 64 + k) * 64 + ct * 32 + c4];
            }
        } else {
            const float4* W4 = (const float4*)Wc;
            #pragma unroll
            for (int idx = tid; idx < 2048; idx += 256) {
                int k = idx >> 5, c4 = idx & 31;
                *(float4*)&ws[k * 128 + c4 * 4] = W4[(c * 64 + k) * 32 + c4];
            }
        }
        __syncthreads();

        const float4*     a4 = (const float4*)xsT;
        const ulonglong2* b2 = (const ulonglong2*)ws;

        #pragma unroll 4
        for (int k = 0; k < 64; k++) {
            float4 av0 = a4[k * 33 + ty * 2];
            float4 av1 = a4[k * 33 + ty * 2 + 1];
            ulonglong2 b01 = b2[k * 32 + tx * 2];
            ulonglong2 b23 = b2[k * 32 + tx * 2 + 1];
            ull A[8];
            A[0] = dup2(av0.x); A[1] = dup2(av0.y); A[2] = dup2(av0.z); A[3] = dup2(av0.w);
            A[4] = dup2(av1.x); A[5] = dup2(av1.y); A[6] = dup2(av1.z); A[7] = dup2(av1.w);
            #pragma unroll
            for (int i = 0; i < 8; i++) {
                ffma2(acc[i][0], A[i], b01.x);
                ffma2(acc[i][1], A[i], b01.y);
                ffma2(acc[i][2], A[i], b23.x);
                ffma2(acc[i][3], A[i], b23.y);
            }
        }
        __syncthreads();
    }

    #pragma unroll
    for (int i = 0; i < 8; i++) {
        int vr = r0 + ty * 8 + i;
        if (vr >= total) continue;
        float2 p0 = unpack2(acc[i][0]);
        float2 p1 = unpack2(acc[i][1]);
        float2 p2 = unpack2(acc[i][2]);
        float2 p3 = unpack2(acc[i][3]);
        float* dst = &g_xproj[(size_t)vr * NXC + ct * 128 + tx * 8];
        ((float4*)dst)[0] = make_float4(p0.x, p0.y, p1.x, p1.y);
        ((float4*)dst)[1] = make_float4(p2.x, p2.y, p3.x, p3.y);
    }
}

// =====================================================================
// Phase 2 (R7 structure): GRU on sorted 4-row groups. 256 CTAs x 512 thr.
// xproj now read at COMPACT offsets (coff[sorted_pos] + t).
// =====================================================================
__global__ void __launch_bounds__(512, 1) dien_gru_kernel(
    const float* __restrict__ Wg, const float* __restrict__ Wc,
    const int* __restrict__ seqlen, float* __restrict__ out)
{
    extern __shared__ char smraw[];
    float* whc = (float*)smraw;                 // [128 k][128 col]   65536 B
    ull*   hp  = (ull*)(smraw + 65536);         // [2 pair][128 k]     2048 B
    ull*   rhp = hp + 256;                      // [2 pair][128 k]     2048 B
    ull*   red = rhp + 256;                     // 4096 ull           32768 B

    const int tid = threadIdx.x;
    const int jc  = tid & 127;
    const int q   = tid >> 7;            // 0..3, k-split 32
    const int k0  = q * 32;

    for (int i = tid; i < 128 * 128; i += 512) whc[i] = Wc[128 * 128 + i];

    float wgr[32], wgu[32];
    #pragma unroll
    for (int i = 0; i < 32; i++) {
        wgr[i] = Wg[(size_t)(128 + k0 + i) * 256 + jc];
        wgu[i] = Wg[(size_t)(128 + k0 + i) * 256 + jc + 128];
    }

    const int g  = blockIdx.x;
    const int rA0 = g_perm[4 * g];
    const int maxseq = seqlen[rA0];      // sorted desc -> first is max

    // epilogue threads: q<2 own pair P=q; sorted positions 4g+2q, 4g+2q+1
    const int posA = 4 * g + 2 * (q & 1);
    const int posB = posA + 1;
    const int rowA = g_perm[(q < 2) ? posA : 4 * g];
    const int rowB = g_perm[(q < 2) ? posB : 4 * g];
    const int cofA = g_coff[(q < 2) ? posA : 4 * g];
    const int cofB = g_coff[(q < 2) ? posB : 4 * g];
    const int sqa = seqlen[rowA];
    const int sqb = seqlen[rowB];

    if (tid < 256) hp[tid] = 0ull;
    __syncthreads();

    const float* xa = g_xproj + (size_t)cofA * NXC + jc;
    const float* xb = g_xproj + (size_t)cofB * NXC + jc;
    float* oa = out + (size_t)rowA * TLEN * HDIM + jc;
    float* ob = out + (size_t)rowB * TLEN * HDIM + jc;

    const ulonglong2* h2 = (const ulonglong2*)hp  + (k0 >> 1);
    const ulonglong2* r2 = (const ulonglong2*)rhp + (k0 >> 1);
    const float* wcp = whc + k0 * 128 + jc;

    for (int t = 0; t < maxseq; t++) {
        float xra = 0.f, xrb = 0.f, xua = 0.f, xub = 0.f, xca = 0.f, xcb = 0.f;
        if (q < 2) {
            const float* p0 = xa + (size_t)t * NXC;
            const float* p1 = xb + (size_t)t * NXC;
            if (t < sqa) { xra = p0[0]; xua = p0[128]; xca = p0[256]; }
            if (t < sqb) { xrb = p1[0]; xub = p1[128]; xcb = p1[256]; }
        }

        // ---- gate GEMV: 2 gates x 2 pairs, 32 k from regs ----
        ull ar0 = 0, ar1 = 0, au0 = 0, au1 = 0;
        #pragma unroll
        for (int i = 0; i < 16; i++) {
            ulonglong2 a0 = h2[i];
            ulonglong2 a1 = h2[64 + i];
            ull w0 = dup2(wgr[2 * i]), w1 = dup2(wgr[2 * i + 1]);
            ull v0 = dup2(wgu[2 * i]), v1 = dup2(wgu[2 * i + 1]);
            ffma2(ar0, a0.x, w0); ffma2(ar0, a0.y, w1);
            ffma2(ar1, a1.x, w0); ffma2(ar1, a1.y, w1);
            ffma2(au0, a0.x, v0); ffma2(au0, a0.y, v1);
            ffma2(au1, a1.x, v0); ffma2(au1, a1.y, v1);
        }
        {
            ull* st = red + q * 1024 + jc;
            st[0]   = ar0; st[128] = ar1;
            st[512] = au0; st[640] = au1;
        }
        __syncthreads();

        float r_a, r_b, u_a, u_b; float2 Ho;
        if (q < 2) {
            const ull* rd = red + q * 128 + jc;
            ull zr = rd[0], zu = rd[512];
            #pragma unroll
            for (int qq = 1; qq < 4; qq++) {
                zr = addf2(zr, rd[qq * 1024]);
                zu = addf2(zu, rd[qq * 1024 + 512]);
            }
            float2 Zr = unpack2(zr), Zu = unpack2(zu);
            r_a = sigap(Zr.x + xra); r_b = sigap(Zr.y + xrb);
            u_a = sigap(Zu.x + xua); u_b = sigap(Zu.y + xub);
            Ho = unpack2(hp[q * 128 + jc]);
            rhp[q * 128 + jc] = pack2(r_a * Ho.x, r_b * Ho.y);
        }
        __syncthreads();

        // ---- cand GEMV: 2 pairs, 32 k, weights from smem ----
        ull c0 = 0, c1 = 0;
        #pragma unroll
        for (int i = 0; i < 16; i++) {
            ulonglong2 a0 = r2[i];
            ulonglong2 a1 = r2[64 + i];
            ull w0 = dup2(wcp[(2 * i) * 128]);
            ull w1 = dup2(wcp[(2 * i + 1) * 128]);
            ffma2(c0, a0.x, w0); ffma2(c0, a0.y, w1);
            ffma2(c1, a1.x, w0); ffma2(c1, a1.y, w1);
        }
        {
            ull* st = red + q * 256 + jc;
            st[0] = c0; st[128] = c1;
        }
        __syncthreads();

        if (q < 2) {
            const ull* rd = red + q * 128 + jc;
            ull zc = rd[0];
            #pragma unroll
            for (int qq = 1; qq < 4; qq++) zc = addf2(zc, rd[qq * 256]);
            float2 Zc = unpack2(zc);
            float c_a = tanhap(Zc.x + xca);
            float c_b = tanhap(Zc.y + xcb);
            float hna = fmaf(u_a, Ho.x - c_a, c_a);
            float hnb = fmaf(u_b, Ho.y - c_b, c_b);
            bool va = t < sqa, vb = t < sqb;
            hp[q * 128 + jc] = pack2(va ? hna : Ho.x, vb ? hnb : Ho.y);
            if (va) oa[(size_t)t * HDIM] = hna;
            if (vb) ob[(size_t)t * HDIM] = hnb;
        }
        __syncthreads();
    }
}

// =====================================================================
extern "C" void kernel_launch(void* const* d_in, const int* in_sizes, int n_in,
                              void* d_out, int out_size)
{
    const float* X   = (const float*)d_in[0];
    const int*   seq = (const int*)  d_in[1];
    const float* Wg  = (const float*)d_in[2];
    const float* bg  = (const float*)d_in[3];
    const float* Wc  = (const float*)d_in[4];
    const float* bc  = (const float*)d_in[5];
    float* out = (float*)d_out;
    (void)in_sizes; (void)n_in;

    const int SMEM1 = (64 * 132 + 64 * 128) * 4;          // 66560 B
    const int SMEM2 = 65536 + 2048 + 2048 + 32768;        // 102400 B
    cudaFuncSetAttribute(dien_xproj_kernel, cudaFuncAttributeMaxDynamicSharedMemorySize, SMEM1);
    cudaFuncSetAttribute(dien_gru_kernel,   cudaFuncAttributeMaxDynamicSharedMemorySize, SMEM2);

    cudaMemsetAsync(d_out, 0, (size_t)out_size * sizeof(float));

    dien_sort_kernel<<<1, 1024>>>(seq);
    dim3 g1(3, 1600);    // worst-case compact rows; tail CTAs exit early
    dien_xproj_kernel<<<g1, 256, SMEM1>>>(X, Wg, bg, Wc, bc);
    dien_gru_kernel<<<GROUPS, 512, SMEM2>>>(Wg, Wc, seq, out);
}